// round 1
// baseline (speedup 1.0000x reference)
#include <cuda_runtime.h>
#include <cuda_bf16.h>
#include <math.h>

// Problem constants
#define NB 8
#define SS 1024
#define DD 512
#define NH 8
#define DK 64
#define MROWS (NB * SS)          // 8192
#define OUT_ELEMS (NB * SS * DD) // 4194304

// Scratch (no allocations allowed)
__device__ float g_qh[MROWS * DD];   // [B,S,H*DK]
__device__ float g_kh[MROWS * DD];
__device__ float g_vs[MROWS * DK];   // [B,S,DK]
__device__ float g_pavg[NB * SS * SS]; // [B,Sq,Sk]
__device__ float g_head[MROWS * DK];

// ---------------------------------------------------------------------------
// Generic tiled GEMM, C[M,N] = A[M,K] * W[N,K]^T   (all row-major)
// BM=BN=64, BK=16, 256 threads, 4x4 register tile per thread.
// Requires M%64==0, N%64==0, K%16==0 (true for all our shapes).
// ---------------------------------------------------------------------------
#define BM 64
#define BN 64
#define BK 16

__global__ void gemm_nt(const float* __restrict__ A, const float* __restrict__ W,
                        float* __restrict__ C, int M, int N, int K) {
    __shared__ float As[BK][BM + 4];
    __shared__ float Ws[BK][BN + 4];
    const int n0 = blockIdx.x * BN;
    const int m0 = blockIdx.y * BM;
    const int tid = threadIdx.x;
    const int tr = tid >> 4;        // 0..15
    const int tc = tid & 15;        // 0..15

    float acc[4][4] = {};
    const int lr = tid >> 2;        // 0..63 (tile row for loads)
    const int lc = (tid & 3) * 4;   // 0,4,8,12 (k offset)

    for (int k0 = 0; k0 < K; k0 += BK) {
        float4 a = *(const float4*)(A + (size_t)(m0 + lr) * K + k0 + lc);
        As[lc + 0][lr] = a.x; As[lc + 1][lr] = a.y;
        As[lc + 2][lr] = a.z; As[lc + 3][lr] = a.w;
        float4 w = *(const float4*)(W + (size_t)(n0 + lr) * K + k0 + lc);
        Ws[lc + 0][lr] = w.x; Ws[lc + 1][lr] = w.y;
        Ws[lc + 2][lr] = w.z; Ws[lc + 3][lr] = w.w;
        __syncthreads();
#pragma unroll
        for (int kk = 0; kk < BK; kk++) {
            float ar[4], wr[4];
#pragma unroll
            for (int i = 0; i < 4; i++) ar[i] = As[kk][tr * 4 + i];
#pragma unroll
            for (int j = 0; j < 4; j++) wr[j] = Ws[kk][tc * 4 + j];
#pragma unroll
            for (int i = 0; i < 4; i++)
#pragma unroll
                for (int j = 0; j < 4; j++) acc[i][j] += ar[i] * wr[j];
        }
        __syncthreads();
    }
#pragma unroll
    for (int i = 0; i < 4; i++)
#pragma unroll
        for (int j = 0; j < 4; j++)
            C[(size_t)(m0 + tr * 4 + i) * N + n0 + tc * 4 + j] = acc[i][j];
}

// ---------------------------------------------------------------------------
// Batched GEMM, C_b[M,N] = A_b[M,K] * B_b[K,N]  (row-major, batch on blockIdx.z)
// M=1024, N=64, K=1024 for P_avg @ vs.
// ---------------------------------------------------------------------------
__global__ void gemm_nn_batched(const float* __restrict__ A, const float* __restrict__ B,
                                float* __restrict__ C, int M, int N, int K,
                                size_t strideA, size_t strideB, size_t strideC) {
    __shared__ float As[BK][BM + 4];
    __shared__ float Bs[BK][BN + 4];
    const float* Ab = A + (size_t)blockIdx.z * strideA;
    const float* Bb = B + (size_t)blockIdx.z * strideB;
    float* Cb = C + (size_t)blockIdx.z * strideC;
    const int n0 = blockIdx.x * BN;
    const int m0 = blockIdx.y * BM;
    const int tid = threadIdx.x;
    const int tr = tid >> 4, tc = tid & 15;

    float acc[4][4] = {};
    const int lr = tid >> 2;
    const int lc = (tid & 3) * 4;
    const int br = tid >> 4;            // 0..15 (k row in B tile)
    const int bc = (tid & 15) * 4;      // 0..60 (n offset)

    for (int k0 = 0; k0 < K; k0 += BK) {
        float4 a = *(const float4*)(Ab + (size_t)(m0 + lr) * K + k0 + lc);
        As[lc + 0][lr] = a.x; As[lc + 1][lr] = a.y;
        As[lc + 2][lr] = a.z; As[lc + 3][lr] = a.w;
        float4 b = *(const float4*)(Bb + (size_t)(k0 + br) * N + n0 + bc);
        Bs[br][bc + 0] = b.x; Bs[br][bc + 1] = b.y;
        Bs[br][bc + 2] = b.z; Bs[br][bc + 3] = b.w;
        __syncthreads();
#pragma unroll
        for (int kk = 0; kk < BK; kk++) {
            float ar[4], wr[4];
#pragma unroll
            for (int i = 0; i < 4; i++) ar[i] = As[kk][tr * 4 + i];
#pragma unroll
            for (int j = 0; j < 4; j++) wr[j] = Bs[kk][tc * 4 + j];
#pragma unroll
            for (int i = 0; i < 4; i++)
#pragma unroll
                for (int j = 0; j < 4; j++) acc[i][j] += ar[i] * wr[j];
        }
        __syncthreads();
    }
#pragma unroll
    for (int i = 0; i < 4; i++)
#pragma unroll
        for (int j = 0; j < 4; j++)
            Cb[(size_t)(m0 + tr * 4 + i) * N + n0 + tc * 4 + j] = acc[i][j];
}

// ---------------------------------------------------------------------------
// Fused scores + softmax. Block: (b, h, 16 query rows). 256 threads.
// Each thread computes 16q x 4k scores in registers, spills to shared,
// warp-parallel row softmax, coalesced write of normalized attn.
// Shared: qs 16*64 + sc 16*1024 floats = 69,632 bytes (dynamic).
// ---------------------------------------------------------------------------
#define TQ 16
#define ATTN_SMEM ((TQ * 64 + TQ * SS) * 4)

__global__ void attn_scores_kernel(const float* __restrict__ qh,
                                   const float* __restrict__ kh,
                                   float* __restrict__ attn_out) {
    extern __shared__ float smem[];
    float* qs = smem;             // [TQ][64]
    float* sc = smem + TQ * 64;   // [TQ][1024]
    const int q0 = blockIdx.x * TQ;
    const int h  = blockIdx.y;
    const int b  = blockIdx.z;
    const int tid = threadIdx.x;

    // load Q rows, pre-scaled by 1/sqrt(dk) = 0.125
    const float* qbase = qh + ((size_t)(b * SS + q0)) * DD + h * DK;
    for (int i = tid; i < TQ * 64; i += 256) {
        int r = i >> 6, e = i & 63;
        qs[r * 64 + e] = qbase[(size_t)r * DD + e] * 0.125f;
    }
    __syncthreads();

    // scores: thread handles keys 4*tid .. 4*tid+3 against all 16 q rows
    const float* kbase = kh + ((size_t)b * SS) * DD + h * DK;
    const int k0 = tid * 4;
    float acc[TQ][4];
#pragma unroll
    for (int qi = 0; qi < TQ; qi++)
#pragma unroll
        for (int j = 0; j < 4; j++) acc[qi][j] = 0.f;

#pragma unroll
    for (int c = 0; c < 16; c++) {
        float4 kr[4];
#pragma unroll
        for (int j = 0; j < 4; j++)
            kr[j] = *(const float4*)(kbase + (size_t)(k0 + j) * DD + c * 4);
#pragma unroll
        for (int qi = 0; qi < TQ; qi++) {
            float4 qv = *(const float4*)(qs + qi * 64 + c * 4);
#pragma unroll
            for (int j = 0; j < 4; j++)
                acc[qi][j] += qv.x * kr[j].x + qv.y * kr[j].y +
                              qv.z * kr[j].z + qv.w * kr[j].w;
        }
    }
#pragma unroll
    for (int qi = 0; qi < TQ; qi++)
#pragma unroll
        for (int j = 0; j < 4; j++) sc[qi * SS + k0 + j] = acc[qi][j];
    __syncthreads();

    // softmax per row: 8 warps, 2 rows each
    const int warp = tid >> 5, lane = tid & 31;
    for (int r = warp; r < TQ; r += 8) {
        float* row = sc + r * SS;
        float m = -1e30f;
        for (int k = lane; k < SS; k += 32) m = fmaxf(m, row[k]);
#pragma unroll
        for (int off = 16; off > 0; off >>= 1)
            m = fmaxf(m, __shfl_xor_sync(0xffffffffu, m, off));
        float s = 0.f;
        for (int k = lane; k < SS; k += 32) {
            float e = __expf(row[k] - m);
            row[k] = e;
            s += e;
        }
#pragma unroll
        for (int off = 16; off > 0; off >>= 1)
            s += __shfl_xor_sync(0xffffffffu, s, off);
        float inv = 1.f / s;
        // attn layout: [H, B, Sq, Sk]
        float* orow = attn_out + (((size_t)(h * NB + b) * SS) + q0 + r) * SS;
        for (int k = lane; k < SS; k += 32) orow[k] = row[k] * inv;
    }
}

// ---------------------------------------------------------------------------
// P_avg[b,q,k] = (1/H) * sum_h attn[h,b,q,k]
// ---------------------------------------------------------------------------
__global__ void pavg_kernel(const float* __restrict__ attn, float* __restrict__ pavg) {
    size_t idx = (size_t)blockIdx.x * 256 + threadIdx.x;  // < 8*1024*1024
    int b = (int)(idx >> 20);
    size_t rem = idx & ((1u << 20) - 1);  // q*1024 + k
    float s = 0.f;
#pragma unroll
    for (int h = 0; h < NH; h++)
        s += attn[(size_t)(h * NB + b) * (SS * SS) + rem];
    pavg[idx] = s * 0.125f;
}

// ---------------------------------------------------------------------------
extern "C" void kernel_launch(void* const* d_in, const int* in_sizes, int n_in,
                              void* d_out, int out_size) {
    const float* q  = (const float*)d_in[0];
    const float* k  = (const float*)d_in[1];
    const float* v  = (const float*)d_in[2];
    const float* Wq = (const float*)d_in[3];
    const float* Wk = (const float*)d_in[4];
    const float* Wv = (const float*)d_in[5];
    const float* Wo = (const float*)d_in[6];
    float* out  = (float*)d_out;
    float* attn = out + OUT_ELEMS;

    float *qh, *kh, *vs, *pavg, *head;
    cudaGetSymbolAddress((void**)&qh,   g_qh);
    cudaGetSymbolAddress((void**)&kh,   g_kh);
    cudaGetSymbolAddress((void**)&vs,   g_vs);
    cudaGetSymbolAddress((void**)&pavg, g_pavg);
    cudaGetSymbolAddress((void**)&head, g_head);

    cudaFuncSetAttribute(attn_scores_kernel,
                         cudaFuncAttributeMaxDynamicSharedMemorySize, ATTN_SMEM);

    // Projections: qh = q @ Wq^T (flattened [512,512]), kh likewise, vs = v @ Wv^T
    gemm_nt<<<dim3(DD / BN, MROWS / BM), 256>>>(q, Wq, qh, MROWS, DD, DD);
    gemm_nt<<<dim3(DD / BN, MROWS / BM), 256>>>(k, Wk, kh, MROWS, DD, DD);
    gemm_nt<<<dim3(DK / BN, MROWS / BM), 256>>>(v, Wv, vs, MROWS, DK, DD);

    // Scores + softmax, writes normalized attn straight into d_out
    attn_scores_kernel<<<dim3(SS / TQ, NH, NB), 256, ATTN_SMEM>>>(qh, kh, attn);

    // Mean over heads
    pavg_kernel<<<(NB * SS * SS) / 256, 256>>>(attn, pavg);

    // head = P_avg @ vs   (per batch)
    gemm_nn_batched<<<dim3(DK / BN, SS / BM, NB), 256>>>(
        pavg, vs, head, SS, DK, SS,
        (size_t)SS * SS, (size_t)SS * DK, (size_t)SS * DK);

    // out = head @ Wo^T
    gemm_nt<<<dim3(DD / BN, MROWS / BM), 256>>>(head, Wo, out, MROWS, DD, DK);
}

// round 3
// speedup vs baseline: 1.0932x; 1.0932x over previous
#include <cuda_runtime.h>
#include <cuda_bf16.h>
#include <math.h>
#include <stdint.h>

// Problem constants
#define NB 8
#define SS 1024
#define DD 512
#define NH 8
#define DK 64
#define MROWS (NB * SS)          // 8192
#define OUT_ELEMS (NB * SS * DD) // 4194304

// Scratch (no allocations allowed)
__device__ float g_qh[MROWS * DD];     // [B,S,H*DK]
__device__ float g_kh[MROWS * DD];
__device__ float g_vs[MROWS * DK];     // [B,S,DK]
__device__ float g_pavg[NB * SS * SS]; // [B,Sq,Sk]
__device__ float g_head[MROWS * DK];

// ---------------------------------------------------------------------------
// tf32 helpers
// ---------------------------------------------------------------------------
__device__ __forceinline__ uint32_t f2tf32(float x) {
    uint32_t r;
    asm("cvt.rna.tf32.f32 %0, %1;" : "=r"(r) : "f"(x));
    return r;
}

__device__ __forceinline__ void mma_tf32(float* d, const uint32_t* a,
                                         const uint32_t* b, const float* c) {
    asm volatile(
        "mma.sync.aligned.m16n8k8.row.col.f32.tf32.tf32.f32 "
        "{%0,%1,%2,%3}, {%4,%5,%6,%7}, {%8,%9}, {%10,%11,%12,%13};"
        : "=f"(d[0]), "=f"(d[1]), "=f"(d[2]), "=f"(d[3])
        : "r"(a[0]), "r"(a[1]), "r"(a[2]), "r"(a[3]),
          "r"(b[0]), "r"(b[1]),
          "f"(c[0]), "f"(c[1]), "f"(c[2]), "f"(c[3]));
}

// ---------------------------------------------------------------------------
// MMA GEMM-NT: C[M,N] = A[M,K] * W[N,K]^T (row-major). tf32 compute.
// BM=128, BN=64, BK=32. 256 threads = 8 warps in 4(M) x 2(N); warp tile 32x32.
// Smem row stride 36 (== 4 mod 32) -> conflict-free fragment loads.
// Requires M%128==0, N%64==0, K%32==0.
// ---------------------------------------------------------------------------
#define GST 36

__global__ void gemm_nt_mma(const float* __restrict__ A, const float* __restrict__ W,
                            float* __restrict__ C, int M, int N, int K) {
    __shared__ uint32_t As[128 * GST];
    __shared__ uint32_t Ws[64 * GST];
    const int m0 = blockIdx.y * 128;
    const int n0 = blockIdx.x * 64;
    const int tid = threadIdx.x;
    const int wid = tid >> 5, lane = tid & 31;
    const int lr = lane >> 2, lc = lane & 3;
    const int wm = (wid >> 1) * 32;  // 0,32,64,96
    const int wn = (wid & 1) * 32;   // 0,32

    float acc[2][4][4] = {};

    for (int k0 = 0; k0 < K; k0 += 32) {
        // Load A tile 128x32 (tf32-converted)
#pragma unroll
        for (int s = tid; s < 128 * 8; s += 256) {
            int r = s >> 3, c4 = (s & 7) * 4;
            float4 v = *(const float4*)(A + (size_t)(m0 + r) * K + k0 + c4);
            As[r * GST + c4 + 0] = f2tf32(v.x);
            As[r * GST + c4 + 1] = f2tf32(v.y);
            As[r * GST + c4 + 2] = f2tf32(v.z);
            As[r * GST + c4 + 3] = f2tf32(v.w);
        }
        // Load W tile 64x32
#pragma unroll
        for (int s = tid; s < 64 * 8; s += 256) {
            int r = s >> 3, c4 = (s & 7) * 4;
            float4 v = *(const float4*)(W + (size_t)(n0 + r) * K + k0 + c4);
            Ws[r * GST + c4 + 0] = f2tf32(v.x);
            Ws[r * GST + c4 + 1] = f2tf32(v.y);
            Ws[r * GST + c4 + 2] = f2tf32(v.z);
            Ws[r * GST + c4 + 3] = f2tf32(v.w);
        }
        __syncthreads();
#pragma unroll
        for (int kk = 0; kk < 32; kk += 8) {
            uint32_t a[2][4], b[4][2];
#pragma unroll
            for (int mi = 0; mi < 2; mi++) {
                int r0 = wm + mi * 16 + lr;
                a[mi][0] = As[r0 * GST + kk + lc];
                a[mi][1] = As[(r0 + 8) * GST + kk + lc];
                a[mi][2] = As[r0 * GST + kk + lc + 4];
                a[mi][3] = As[(r0 + 8) * GST + kk + lc + 4];
            }
#pragma unroll
            for (int nj = 0; nj < 4; nj++) {
                int rn = wn + nj * 8 + lr;
                b[nj][0] = Ws[rn * GST + kk + lc];
                b[nj][1] = Ws[rn * GST + kk + lc + 4];
            }
#pragma unroll
            for (int mi = 0; mi < 2; mi++)
#pragma unroll
                for (int nj = 0; nj < 4; nj++)
                    mma_tf32(acc[mi][nj], a[mi], b[nj], acc[mi][nj]);
        }
        __syncthreads();
    }
    // Epilogue
#pragma unroll
    for (int mi = 0; mi < 2; mi++) {
        int row = m0 + wm + mi * 16 + lr;
#pragma unroll
        for (int nj = 0; nj < 4; nj++) {
            int col = n0 + wn + nj * 8 + 2 * lc;
            *(float2*)(C + (size_t)row * N + col) =
                make_float2(acc[mi][nj][0], acc[mi][nj][1]);
            *(float2*)(C + (size_t)(row + 8) * N + col) =
                make_float2(acc[mi][nj][2], acc[mi][nj][3]);
        }
    }
}

// ---------------------------------------------------------------------------
// Batched fp32 GEMM, C_b[M,N] = A_b[M,K] * B_b[K,N] (row-major)
// ---------------------------------------------------------------------------
#define BM 64
#define BN 64
#define BK 16

__global__ void gemm_nn_batched(const float* __restrict__ A, const float* __restrict__ B,
                                float* __restrict__ C, int M, int N, int K,
                                size_t strideA, size_t strideB, size_t strideC) {
    __shared__ float As[BK][BM + 4];
    __shared__ float Bs[BK][BN + 4];
    const float* Ab = A + (size_t)blockIdx.z * strideA;
    const float* Bb = B + (size_t)blockIdx.z * strideB;
    float* Cb = C + (size_t)blockIdx.z * strideC;
    const int n0 = blockIdx.x * BN;
    const int m0 = blockIdx.y * BM;
    const int tid = threadIdx.x;
    const int tr = tid >> 4, tc = tid & 15;

    float acc[4][4] = {};
    const int lr = tid >> 2;
    const int lc = (tid & 3) * 4;
    const int br = tid >> 4;
    const int bc = (tid & 15) * 4;

    for (int k0 = 0; k0 < K; k0 += BK) {
        float4 a = *(const float4*)(Ab + (size_t)(m0 + lr) * K + k0 + lc);
        As[lc + 0][lr] = a.x; As[lc + 1][lr] = a.y;
        As[lc + 2][lr] = a.z; As[lc + 3][lr] = a.w;
        float4 b = *(const float4*)(Bb + (size_t)(k0 + br) * N + n0 + bc);
        Bs[br][bc + 0] = b.x; Bs[br][bc + 1] = b.y;
        Bs[br][bc + 2] = b.z; Bs[br][bc + 3] = b.w;
        __syncthreads();
#pragma unroll
        for (int kk = 0; kk < BK; kk++) {
            float ar[4], wr[4];
#pragma unroll
            for (int i = 0; i < 4; i++) ar[i] = As[kk][tr * 4 + i];
#pragma unroll
            for (int j = 0; j < 4; j++) wr[j] = Bs[kk][tc * 4 + j];
#pragma unroll
            for (int i = 0; i < 4; i++)
#pragma unroll
                for (int j = 0; j < 4; j++) acc[i][j] += ar[i] * wr[j];
        }
        __syncthreads();
    }
#pragma unroll
    for (int i = 0; i < 4; i++)
#pragma unroll
        for (int j = 0; j < 4; j++)
            Cb[(size_t)(m0 + tr * 4 + i) * N + n0 + tc * 4 + j] = acc[i][j];
}

// ---------------------------------------------------------------------------
// Fused scores (tf32 MMA) + softmax. Block: (b, h, 32 q rows). 256 threads.
// Loops over 8 key chunks of 128; each warp computes a 32q x 16k sub-tile.
// Smem: qs[32][68] + ks[128][68] tf32, sc[32][1024] fp32 = 170.5 KB dynamic.
// ---------------------------------------------------------------------------
#define TQ 32
#define QST 68  // 64 + 4, stride == 4 mod 32 -> conflict-free frag loads
#define ATTN_SMEM ((TQ * QST + 128 * QST + TQ * SS) * 4)

__global__ void attn_scores_kernel(const float* __restrict__ qh,
                                   const float* __restrict__ kh,
                                   float* __restrict__ attn_out) {
    extern __shared__ uint32_t smem_u[];
    uint32_t* qs = smem_u;                 // [32][QST]
    uint32_t* ks = smem_u + TQ * QST;      // [128][QST]
    float* sc = (float*)(smem_u + TQ * QST + 128 * QST);  // [32][1024]

    const int q0 = blockIdx.x * TQ;
    const int h = blockIdx.y;
    const int b = blockIdx.z;
    const int tid = threadIdx.x;
    const int wid = tid >> 5, lane = tid & 31;
    const int lr = lane >> 2, lc = lane & 3;

    // Load 32 Q rows (pre-scaled by 1/sqrt(dk)=0.125, tf32-converted)
    const float* qbase = qh + ((size_t)(b * SS + q0)) * DD + h * DK;
#pragma unroll
    for (int s = tid; s < TQ * 16; s += 256) {
        int r = s >> 4, c4 = (s & 15) * 4;
        float4 v = *(const float4*)(qbase + (size_t)r * DD + c4);
        qs[r * QST + c4 + 0] = f2tf32(v.x * 0.125f);
        qs[r * QST + c4 + 1] = f2tf32(v.y * 0.125f);
        qs[r * QST + c4 + 2] = f2tf32(v.z * 0.125f);
        qs[r * QST + c4 + 3] = f2tf32(v.w * 0.125f);
    }

    const float* kbase = kh + ((size_t)b * SS) * DD + h * DK;

    for (int ck = 0; ck < SS / 128; ck++) {
        __syncthreads();
        // Load K chunk: 128 keys x 64
#pragma unroll
        for (int s = tid; s < 128 * 16; s += 256) {
            int r = s >> 4, c4 = (s & 15) * 4;
            float4 v = *(const float4*)(kbase + (size_t)(ck * 128 + r) * DD + c4);
            ks[r * QST + c4 + 0] = f2tf32(v.x);
            ks[r * QST + c4 + 1] = f2tf32(v.y);
            ks[r * QST + c4 + 2] = f2tf32(v.z);
            ks[r * QST + c4 + 3] = f2tf32(v.w);
        }
        __syncthreads();

        float acc[2][2][4] = {};
#pragma unroll
        for (int kk = 0; kk < DK; kk += 8) {
            uint32_t a[2][4], bfr[2][2];
#pragma unroll
            for (int mi = 0; mi < 2; mi++) {
                int r0 = mi * 16 + lr;
                a[mi][0] = qs[r0 * QST + kk + lc];
                a[mi][1] = qs[(r0 + 8) * QST + kk + lc];
                a[mi][2] = qs[r0 * QST + kk + lc + 4];
                a[mi][3] = qs[(r0 + 8) * QST + kk + lc + 4];
            }
#pragma unroll
            for (int nj = 0; nj < 2; nj++) {
                int rn = wid * 16 + nj * 8 + lr;
                bfr[nj][0] = ks[rn * QST + kk + lc];
                bfr[nj][1] = ks[rn * QST + kk + lc + 4];
            }
#pragma unroll
            for (int mi = 0; mi < 2; mi++)
#pragma unroll
                for (int nj = 0; nj < 2; nj++)
                    mma_tf32(acc[mi][nj], a[mi], bfr[nj], acc[mi][nj]);
        }
        // Store scores to smem
#pragma unroll
        for (int mi = 0; mi < 2; mi++) {
            int row = mi * 16 + lr;
#pragma unroll
            for (int nj = 0; nj < 2; nj++) {
                int col = ck * 128 + wid * 16 + nj * 8 + 2 * lc;
                *(float2*)(sc + (size_t)row * SS + col) =
                    make_float2(acc[mi][nj][0], acc[mi][nj][1]);
                *(float2*)(sc + (size_t)(row + 8) * SS + col) =
                    make_float2(acc[mi][nj][2], acc[mi][nj][3]);
            }
        }
    }
    __syncthreads();

    // Softmax: each warp handles 4 rows
    for (int r = wid; r < TQ; r += 8) {
        float* row = sc + (size_t)r * SS;
        float m = -1e30f;
        for (int k = lane; k < SS; k += 32) m = fmaxf(m, row[k]);
#pragma unroll
        for (int off = 16; off > 0; off >>= 1)
            m = fmaxf(m, __shfl_xor_sync(0xffffffffu, m, off));
        float s = 0.f;
        for (int k = lane; k < SS; k += 32) {
            float e = __expf(row[k] - m);
            row[k] = e;
            s += e;
        }
#pragma unroll
        for (int off = 16; off > 0; off >>= 1)
            s += __shfl_xor_sync(0xffffffffu, s, off);
        float inv = 1.f / s;
        float* orow = attn_out + (((size_t)(h * NB + b) * SS) + q0 + r) * SS;
        for (int k = lane; k < SS; k += 32) orow[k] = row[k] * inv;
    }
}

// ---------------------------------------------------------------------------
// P_avg[b,q,k] = (1/H) * sum_h attn[h,b,q,k]
// ---------------------------------------------------------------------------
__global__ void pavg_kernel(const float* __restrict__ attn, float* __restrict__ pavg) {
    size_t idx = (size_t)blockIdx.x * 256 + threadIdx.x;
    int b = (int)(idx >> 20);
    size_t rem = idx & ((1u << 20) - 1);
    float s = 0.f;
#pragma unroll
    for (int h = 0; h < NH; h++)
        s += attn[(size_t)(h * NB + b) * (SS * SS) + rem];
    pavg[idx] = s * 0.125f;
}

// ---------------------------------------------------------------------------
extern "C" void kernel_launch(void* const* d_in, const int* in_sizes, int n_in,
                              void* d_out, int out_size) {
    const float* q  = (const float*)d_in[0];
    const float* k  = (const float*)d_in[1];
    const float* v  = (const float*)d_in[2];
    const float* Wq = (const float*)d_in[3];
    const float* Wk = (const float*)d_in[4];
    const float* Wv = (const float*)d_in[5];
    const float* Wo = (const float*)d_in[6];
    float* out  = (float*)d_out;
    float* attn = out + OUT_ELEMS;

    float *qh, *kh, *vs, *pavg, *head;
    cudaGetSymbolAddress((void**)&qh,   g_qh);
    cudaGetSymbolAddress((void**)&kh,   g_kh);
    cudaGetSymbolAddress((void**)&vs,   g_vs);
    cudaGetSymbolAddress((void**)&pavg, g_pavg);
    cudaGetSymbolAddress((void**)&head, g_head);

    cudaFuncSetAttribute(attn_scores_kernel,
                         cudaFuncAttributeMaxDynamicSharedMemorySize, ATTN_SMEM);

    // Projections via tf32 MMA
    gemm_nt_mma<<<dim3(DD / 64, MROWS / 128), 256>>>(q, Wq, qh, MROWS, DD, DD);
    gemm_nt_mma<<<dim3(DD / 64, MROWS / 128), 256>>>(k, Wk, kh, MROWS, DD, DD);
    gemm_nt_mma<<<dim3(DK / 64, MROWS / 128), 256>>>(v, Wv, vs, MROWS, DK, DD);

    // Scores + softmax -> attn (in d_out)
    attn_scores_kernel<<<dim3(SS / TQ, NH, NB), 256, ATTN_SMEM>>>(qh, kh, attn);

    // Mean over heads
    pavg_kernel<<<(NB * SS * SS) / 256, 256>>>(attn, pavg);

    // head = P_avg @ vs (per batch), fp32
    gemm_nn_batched<<<dim3(DK / BN, SS / BM, NB), 256>>>(
        pavg, vs, head, SS, DK, SS,
        (size_t)SS * SS, (size_t)SS * DK, (size_t)SS * DK);

    // out = head @ Wo^T via tf32 MMA (K=64)
    gemm_nt_mma<<<dim3(DD / 64, MROWS / 128), 256>>>(head, Wo, out, MROWS, DD, DK);
}

// round 4
// speedup vs baseline: 1.5777x; 1.4432x over previous
#include <cuda_runtime.h>
#include <cuda_bf16.h>
#include <math.h>
#include <stdint.h>

// Problem constants
#define NB 8
#define SS 1024
#define DD 512
#define NH 8
#define DK 64
#define MROWS (NB * SS)          // 8192
#define OUT_ELEMS (NB * SS * DD) // 4194304

// Scratch (no allocations allowed)
__device__ float g_qh[MROWS * DD];     // [B,S,H*DK]
__device__ float g_kh[MROWS * DD];
__device__ float g_vs[MROWS * DK];     // [B,S,DK]
__device__ float g_pavg[NB * SS * SS]; // [B,Sq,Sk]
__device__ float g_head[MROWS * DK];

// ---------------------------------------------------------------------------
// tf32 helpers
// ---------------------------------------------------------------------------
__device__ __forceinline__ uint32_t f2tf32(float x) {
    uint32_t r;
    asm("cvt.rna.tf32.f32 %0, %1;" : "=r"(r) : "f"(x));
    return r;
}

__device__ __forceinline__ void mma_tf32(float* d, const uint32_t* a,
                                         const uint32_t* b, const float* c) {
    asm volatile(
        "mma.sync.aligned.m16n8k8.row.col.f32.tf32.tf32.f32 "
        "{%0,%1,%2,%3}, {%4,%5,%6,%7}, {%8,%9}, {%10,%11,%12,%13};"
        : "=f"(d[0]), "=f"(d[1]), "=f"(d[2]), "=f"(d[3])
        : "r"(a[0]), "r"(a[1]), "r"(a[2]), "r"(a[3]),
          "r"(b[0]), "r"(b[1]),
          "f"(c[0]), "f"(c[1]), "f"(c[2]), "f"(c[3]));
}

// ---------------------------------------------------------------------------
// MMA GEMM-NT: C[M,N] = A[M,K] * W[N,K]^T (row-major). tf32 compute.
// BM=128, BN=64, BK=32. 256 threads = 8 warps in 4(M) x 2(N); warp tile 32x32.
// ---------------------------------------------------------------------------
#define GST 36

__global__ void gemm_nt_mma(const float* __restrict__ A, const float* __restrict__ W,
                            float* __restrict__ C, int M, int N, int K) {
    __shared__ uint32_t As[128 * GST];
    __shared__ uint32_t Ws[64 * GST];
    const int m0 = blockIdx.y * 128;
    const int n0 = blockIdx.x * 64;
    const int tid = threadIdx.x;
    const int wid = tid >> 5, lane = tid & 31;
    const int lr = lane >> 2, lc = lane & 3;
    const int wm = (wid >> 1) * 32;
    const int wn = (wid & 1) * 32;

    float acc[2][4][4] = {};

    for (int k0 = 0; k0 < K; k0 += 32) {
#pragma unroll
        for (int s = tid; s < 128 * 8; s += 256) {
            int r = s >> 3, c4 = (s & 7) * 4;
            float4 v = *(const float4*)(A + (size_t)(m0 + r) * K + k0 + c4);
            As[r * GST + c4 + 0] = f2tf32(v.x);
            As[r * GST + c4 + 1] = f2tf32(v.y);
            As[r * GST + c4 + 2] = f2tf32(v.z);
            As[r * GST + c4 + 3] = f2tf32(v.w);
        }
#pragma unroll
        for (int s = tid; s < 64 * 8; s += 256) {
            int r = s >> 3, c4 = (s & 7) * 4;
            float4 v = *(const float4*)(W + (size_t)(n0 + r) * K + k0 + c4);
            Ws[r * GST + c4 + 0] = f2tf32(v.x);
            Ws[r * GST + c4 + 1] = f2tf32(v.y);
            Ws[r * GST + c4 + 2] = f2tf32(v.z);
            Ws[r * GST + c4 + 3] = f2tf32(v.w);
        }
        __syncthreads();
#pragma unroll
        for (int kk = 0; kk < 32; kk += 8) {
            uint32_t a[2][4], b[4][2];
#pragma unroll
            for (int mi = 0; mi < 2; mi++) {
                int r0 = wm + mi * 16 + lr;
                a[mi][0] = As[r0 * GST + kk + lc];
                a[mi][1] = As[(r0 + 8) * GST + kk + lc];
                a[mi][2] = As[r0 * GST + kk + lc + 4];
                a[mi][3] = As[(r0 + 8) * GST + kk + lc + 4];
            }
#pragma unroll
            for (int nj = 0; nj < 4; nj++) {
                int rn = wn + nj * 8 + lr;
                b[nj][0] = Ws[rn * GST + kk + lc];
                b[nj][1] = Ws[rn * GST + kk + lc + 4];
            }
#pragma unroll
            for (int mi = 0; mi < 2; mi++)
#pragma unroll
                for (int nj = 0; nj < 4; nj++)
                    mma_tf32(acc[mi][nj], a[mi], b[nj], acc[mi][nj]);
        }
        __syncthreads();
    }
#pragma unroll
    for (int mi = 0; mi < 2; mi++) {
        int row = m0 + wm + mi * 16 + lr;
#pragma unroll
        for (int nj = 0; nj < 4; nj++) {
            int col = n0 + wn + nj * 8 + 2 * lc;
            *(float2*)(C + (size_t)row * N + col) =
                make_float2(acc[mi][nj][0], acc[mi][nj][1]);
            *(float2*)(C + (size_t)(row + 8) * N + col) =
                make_float2(acc[mi][nj][2], acc[mi][nj][3]);
        }
    }
}

// ---------------------------------------------------------------------------
// Batched fp32 GEMM, C_b[M,N] = A_b[M,K] * B_b[K,N] (row-major)
// ---------------------------------------------------------------------------
#define BM 64
#define BN 64
#define BK 16

__global__ void gemm_nn_batched(const float* __restrict__ A, const float* __restrict__ B,
                                float* __restrict__ C, int M, int N, int K,
                                size_t strideA, size_t strideB, size_t strideC) {
    __shared__ float As[BK][BM + 4];
    __shared__ float Bs[BK][BN + 4];
    const float* Ab = A + (size_t)blockIdx.z * strideA;
    const float* Bb = B + (size_t)blockIdx.z * strideB;
    float* Cb = C + (size_t)blockIdx.z * strideC;
    const int n0 = blockIdx.x * BN;
    const int m0 = blockIdx.y * BM;
    const int tid = threadIdx.x;
    const int tr = tid >> 4, tc = tid & 15;

    float acc[4][4] = {};
    const int lr = tid >> 2;
    const int lc = (tid & 3) * 4;
    const int br = tid >> 4;
    const int bc = (tid & 15) * 4;

    for (int k0 = 0; k0 < K; k0 += BK) {
        float4 a = *(const float4*)(Ab + (size_t)(m0 + lr) * K + k0 + lc);
        As[lc + 0][lr] = a.x; As[lc + 1][lr] = a.y;
        As[lc + 2][lr] = a.z; As[lc + 3][lr] = a.w;
        float4 b = *(const float4*)(Bb + (size_t)(k0 + br) * N + n0 + bc);
        Bs[br][bc + 0] = b.x; Bs[br][bc + 1] = b.y;
        Bs[br][bc + 2] = b.z; Bs[br][bc + 3] = b.w;
        __syncthreads();
#pragma unroll
        for (int kk = 0; kk < BK; kk++) {
            float ar[4], wr[4];
#pragma unroll
            for (int i = 0; i < 4; i++) ar[i] = As[kk][tr * 4 + i];
#pragma unroll
            for (int j = 0; j < 4; j++) wr[j] = Bs[kk][tc * 4 + j];
#pragma unroll
            for (int i = 0; i < 4; i++)
#pragma unroll
                for (int j = 0; j < 4; j++) acc[i][j] += ar[i] * wr[j];
        }
        __syncthreads();
    }
#pragma unroll
    for (int i = 0; i < 4; i++)
#pragma unroll
        for (int j = 0; j < 4; j++)
            Cb[(size_t)(m0 + tr * 4 + i) * N + n0 + tc * 4 + j] = acc[i][j];
}

// ---------------------------------------------------------------------------
// Fused scores + softmax, register-resident, two-pass (no max: scores are
// O(1) by construction — exp cannot overflow; softmax is shift-invariant).
// Block: 128 q rows x (h, b). 8 warps; warp w owns q rows [w*16, w*16+16).
// Loops over 8 key chunks of 128 in smem. Pass 1 accumulates row sums of
// exp(score); pass 2 recomputes and writes normalized attn directly.
// Smem: qs[128][68] + ks[128][68] tf32 = 69,632 B. 2 CTAs/SM.
// ---------------------------------------------------------------------------
#define QST 68
#define ATTN_SMEM (2 * 128 * QST * 4)

__global__ __launch_bounds__(256, 2)
void attn_scores_kernel(const float* __restrict__ qh,
                        const float* __restrict__ kh,
                        float* __restrict__ attn_out) {
    extern __shared__ uint32_t smem_u[];
    uint32_t* qs = smem_u;              // [128][QST]
    uint32_t* ks = smem_u + 128 * QST;  // [128][QST]

    const int q0 = blockIdx.x * 128;
    const int h = blockIdx.y;
    const int b = blockIdx.z;
    const int tid = threadIdx.x;
    const int wid = tid >> 5, lane = tid & 31;
    const int lr = lane >> 2, lc = lane & 3;
    const int r0 = wid * 16 + lr;  // this thread's first q row (local)

    // Load 128 Q rows (pre-scaled by 1/sqrt(dk)=0.125, tf32)
    const float* qbase = qh + ((size_t)(b * SS + q0)) * DD + h * DK;
#pragma unroll
    for (int s = tid; s < 128 * 16; s += 256) {
        int r = s >> 4, c4 = (s & 15) * 4;
        float4 v = *(const float4*)(qbase + (size_t)r * DD + c4);
        qs[r * QST + c4 + 0] = f2tf32(v.x * 0.125f);
        qs[r * QST + c4 + 1] = f2tf32(v.y * 0.125f);
        qs[r * QST + c4 + 2] = f2tf32(v.z * 0.125f);
        qs[r * QST + c4 + 3] = f2tf32(v.w * 0.125f);
    }

    const float* kbase = kh + ((size_t)b * SS) * DD + h * DK;

    float rsum0 = 0.f, rsum1 = 0.f;

    // ---------------- Pass 1: row sums of exp(score) ----------------
    for (int ck = 0; ck < SS / 128; ck++) {
        __syncthreads();
#pragma unroll
        for (int s = tid; s < 128 * 16; s += 256) {
            int r = s >> 4, c4 = (s & 15) * 4;
            float4 v = *(const float4*)(kbase + (size_t)(ck * 128 + r) * DD + c4);
            ks[r * QST + c4 + 0] = f2tf32(v.x);
            ks[r * QST + c4 + 1] = f2tf32(v.y);
            ks[r * QST + c4 + 2] = f2tf32(v.z);
            ks[r * QST + c4 + 3] = f2tf32(v.w);
        }
        __syncthreads();

        float acc[16][4] = {};
#pragma unroll
        for (int kk = 0; kk < DK; kk += 8) {
            uint32_t a[4];
            a[0] = qs[r0 * QST + kk + lc];
            a[1] = qs[(r0 + 8) * QST + kk + lc];
            a[2] = qs[r0 * QST + kk + lc + 4];
            a[3] = qs[(r0 + 8) * QST + kk + lc + 4];
#pragma unroll
            for (int nj = 0; nj < 16; nj++) {
                uint32_t bf[2];
                int rn = nj * 8 + lr;
                bf[0] = ks[rn * QST + kk + lc];
                bf[1] = ks[rn * QST + kk + lc + 4];
                mma_tf32(acc[nj], a, bf, acc[nj]);
            }
        }
#pragma unroll
        for (int nj = 0; nj < 16; nj++) {
            rsum0 += __expf(acc[nj][0]) + __expf(acc[nj][1]);
            rsum1 += __expf(acc[nj][2]) + __expf(acc[nj][3]);
        }
    }
    // Reduce across the 4 lanes (lc) sharing each row
#pragma unroll
    for (int off = 1; off <= 2; off <<= 1) {
        rsum0 += __shfl_xor_sync(0xffffffffu, rsum0, off);
        rsum1 += __shfl_xor_sync(0xffffffffu, rsum1, off);
    }
    const float inv0 = 1.f / rsum0;
    const float inv1 = 1.f / rsum1;

    // ---------------- Pass 2: recompute, normalize, write ----------------
    float* orow0 = attn_out + (((size_t)(h * NB + b) * SS) + q0 + r0) * SS;
    float* orow1 = orow0 + (size_t)8 * SS;

    for (int ck = 0; ck < SS / 128; ck++) {
        __syncthreads();
#pragma unroll
        for (int s = tid; s < 128 * 16; s += 256) {
            int r = s >> 4, c4 = (s & 15) * 4;
            float4 v = *(const float4*)(kbase + (size_t)(ck * 128 + r) * DD + c4);
            ks[r * QST + c4 + 0] = f2tf32(v.x);
            ks[r * QST + c4 + 1] = f2tf32(v.y);
            ks[r * QST + c4 + 2] = f2tf32(v.z);
            ks[r * QST + c4 + 3] = f2tf32(v.w);
        }
        __syncthreads();

        float acc[16][4] = {};
#pragma unroll
        for (int kk = 0; kk < DK; kk += 8) {
            uint32_t a[4];
            a[0] = qs[r0 * QST + kk + lc];
            a[1] = qs[(r0 + 8) * QST + kk + lc];
            a[2] = qs[r0 * QST + kk + lc + 4];
            a[3] = qs[(r0 + 8) * QST + kk + lc + 4];
#pragma unroll
            for (int nj = 0; nj < 16; nj++) {
                uint32_t bf[2];
                int rn = nj * 8 + lr;
                bf[0] = ks[rn * QST + kk + lc];
                bf[1] = ks[rn * QST + kk + lc + 4];
                mma_tf32(acc[nj], a, bf, acc[nj]);
            }
        }
#pragma unroll
        for (int nj = 0; nj < 16; nj++) {
            int col = ck * 128 + nj * 8 + 2 * lc;
            *(float2*)(orow0 + col) =
                make_float2(__expf(acc[nj][0]) * inv0, __expf(acc[nj][1]) * inv0);
            *(float2*)(orow1 + col) =
                make_float2(__expf(acc[nj][2]) * inv1, __expf(acc[nj][3]) * inv1);
        }
    }
}

// ---------------------------------------------------------------------------
// P_avg[b,q,k] = (1/H) * sum_h attn[h,b,q,k]
// ---------------------------------------------------------------------------
__global__ void pavg_kernel(const float* __restrict__ attn, float* __restrict__ pavg) {
    size_t idx = (size_t)blockIdx.x * 256 + threadIdx.x;
    int b = (int)(idx >> 20);
    size_t rem = idx & ((1u << 20) - 1);
    float s = 0.f;
#pragma unroll
    for (int h = 0; h < NH; h++)
        s += attn[(size_t)(h * NB + b) * (SS * SS) + rem];
    pavg[idx] = s * 0.125f;
}

// ---------------------------------------------------------------------------
extern "C" void kernel_launch(void* const* d_in, const int* in_sizes, int n_in,
                              void* d_out, int out_size) {
    const float* q  = (const float*)d_in[0];
    const float* k  = (const float*)d_in[1];
    const float* v  = (const float*)d_in[2];
    const float* Wq = (const float*)d_in[3];
    const float* Wk = (const float*)d_in[4];
    const float* Wv = (const float*)d_in[5];
    const float* Wo = (const float*)d_in[6];
    float* out  = (float*)d_out;
    float* attn = out + OUT_ELEMS;

    float *qh, *kh, *vs, *pavg, *head;
    cudaGetSymbolAddress((void**)&qh,   g_qh);
    cudaGetSymbolAddress((void**)&kh,   g_kh);
    cudaGetSymbolAddress((void**)&vs,   g_vs);
    cudaGetSymbolAddress((void**)&pavg, g_pavg);
    cudaGetSymbolAddress((void**)&head, g_head);

    cudaFuncSetAttribute(attn_scores_kernel,
                         cudaFuncAttributeMaxDynamicSharedMemorySize, ATTN_SMEM);

    // Projections via tf32 MMA
    gemm_nt_mma<<<dim3(DD / 64, MROWS / 128), 256>>>(q, Wq, qh, MROWS, DD, DD);
    gemm_nt_mma<<<dim3(DD / 64, MROWS / 128), 256>>>(k, Wk, kh, MROWS, DD, DD);
    gemm_nt_mma<<<dim3(DK / 64, MROWS / 128), 256>>>(v, Wv, vs, MROWS, DK, DD);

    // Scores + softmax -> attn (in d_out), register-resident two-pass
    attn_scores_kernel<<<dim3(SS / 128, NH, NB), 256, ATTN_SMEM>>>(qh, kh, attn);

    // Mean over heads
    pavg_kernel<<<(NB * SS * SS) / 256, 256>>>(attn, pavg);

    // head = P_avg @ vs (per batch), fp32
    gemm_nn_batched<<<dim3(DK / BN, SS / BM, NB), 256>>>(
        pavg, vs, head, SS, DK, SS,
        (size_t)SS * SS, (size_t)SS * DK, (size_t)SS * DK);

    // out = head @ Wo^T via tf32 MMA (K=64)
    gemm_nt_mma<<<dim3(DD / 64, MROWS / 128), 256>>>(head, Wo, out, MROWS, DD, DK);
}

// round 5
// speedup vs baseline: 2.3658x; 1.4995x over previous
#include <cuda_runtime.h>
#include <cuda_bf16.h>
#include <math.h>
#include <stdint.h>

// Problem constants
#define NB 8
#define SS 1024
#define DD 512
#define NH 8
#define DK 64
#define MROWS (NB * SS)          // 8192
#define OUT_ELEMS (NB * SS * DD) // 4194304

// Scratch (no allocations allowed)
__device__ float g_qh[MROWS * DD];     // [B,S,H*DK]
__device__ float g_kh[MROWS * DD];
__device__ float g_vs[MROWS * DK];     // [B,S,DK]
__device__ float g_pavg[NB * SS * SS]; // [B,Sq,Sk]
__device__ float g_head[MROWS * DK];

// ---------------------------------------------------------------------------
// tf32 / async helpers
// ---------------------------------------------------------------------------
__device__ __forceinline__ uint32_t f2tf32(float x) {
    uint32_t r;
    asm("cvt.rna.tf32.f32 %0, %1;" : "=r"(r) : "f"(x));
    return r;
}

__device__ __forceinline__ void mma_tf32(float* d, const uint32_t* a,
                                         const uint32_t* b, const float* c) {
    asm volatile(
        "mma.sync.aligned.m16n8k8.row.col.f32.tf32.tf32.f32 "
        "{%0,%1,%2,%3}, {%4,%5,%6,%7}, {%8,%9}, {%10,%11,%12,%13};"
        : "=f"(d[0]), "=f"(d[1]), "=f"(d[2]), "=f"(d[3])
        : "r"(a[0]), "r"(a[1]), "r"(a[2]), "r"(a[3]),
          "r"(b[0]), "r"(b[1]),
          "f"(c[0]), "f"(c[1]), "f"(c[2]), "f"(c[3]));
}

__device__ __forceinline__ void cp_async16(uint32_t dst, const void* src) {
    asm volatile("cp.async.cg.shared.global [%0], [%1], 16;" :: "r"(dst), "l"(src));
}
__device__ __forceinline__ void cp_commit() {
    asm volatile("cp.async.commit_group;");
}
__device__ __forceinline__ void cp_wait1() {
    asm volatile("cp.async.wait_group 1;");
}

// ---------------------------------------------------------------------------
// Pipelined MMA GEMM-NT: C[M,N] = A[M,K] * W[N,K]^T (row-major), tf32.
// BM=128, BN=64, BK=32, 2-stage cp.async double buffer. 256 thr = 8 warps
// (4M x 2N), warp tile 32x32. Smem holds raw fp32; tf32 cvt at fragment load.
// Stage: A 128x36 + W 64x36 floats = 27,648 B; 2 stages = 55,296 B dynamic.
// ---------------------------------------------------------------------------
#define GST 36
#define PROJ_STAGE (192 * GST)             // floats per stage (A then W)
#define PROJ_SMEM (2 * PROJ_STAGE * 4)

__global__ __launch_bounds__(256, 2)
void gemm_nt_mma2(const float* __restrict__ A, const float* __restrict__ W,
                  float* __restrict__ C, int M, int N, int K) {
    extern __shared__ float sm[];
    const int m0 = blockIdx.y * 128;
    const int n0 = blockIdx.x * 64;
    const int tid = threadIdx.x;
    const int wid = tid >> 5, lane = tid & 31;
    const int lr = lane >> 2, lc = lane & 3;
    const int wm = (wid >> 1) * 32;
    const int wn = (wid & 1) * 32;

    const uint32_t smem_base = (uint32_t)__cvta_generic_to_shared(sm);

    float acc[2][4][4] = {};
    const int kt = K / 32;

    // prologue: stage 0
    {
        float* As = sm;
        float* Ws = sm + 128 * GST;
        uint32_t As_u = smem_base;
        uint32_t Ws_u = smem_base + 128 * GST * 4;
#pragma unroll
        for (int t = 0; t < 4; t++) {
            int s = tid + t * 256;                  // 0..1023
            int r = s >> 3, c = (s & 7) * 4;
            cp_async16(As_u + (r * GST + c) * 4, A + (size_t)(m0 + r) * K + c);
        }
#pragma unroll
        for (int t = 0; t < 2; t++) {
            int s = tid + t * 256;                  // 0..511
            int r = s >> 3, c = (s & 7) * 4;
            cp_async16(Ws_u + (r * GST + c) * 4, W + (size_t)(n0 + r) * K + c);
        }
        (void)As; (void)Ws;
    }
    cp_commit();

    for (int it = 0; it < kt; it++) {
        if (it + 1 < kt) {
            int k0 = (it + 1) * 32;
            uint32_t st = smem_base + ((it + 1) & 1) * PROJ_STAGE * 4;
            uint32_t As_u = st;
            uint32_t Ws_u = st + 128 * GST * 4;
#pragma unroll
            for (int t = 0; t < 4; t++) {
                int s = tid + t * 256;
                int r = s >> 3, c = (s & 7) * 4;
                cp_async16(As_u + (r * GST + c) * 4, A + (size_t)(m0 + r) * K + k0 + c);
            }
#pragma unroll
            for (int t = 0; t < 2; t++) {
                int s = tid + t * 256;
                int r = s >> 3, c = (s & 7) * 4;
                cp_async16(Ws_u + (r * GST + c) * 4, W + (size_t)(n0 + r) * K + k0 + c);
            }
        }
        cp_commit();
        cp_wait1();
        __syncthreads();

        const float* As = sm + (it & 1) * PROJ_STAGE;
        const float* Ws = As + 128 * GST;
#pragma unroll
        for (int kk = 0; kk < 32; kk += 8) {
            uint32_t a[2][4], b[4][2];
#pragma unroll
            for (int mi = 0; mi < 2; mi++) {
                int r0 = wm + mi * 16 + lr;
                a[mi][0] = f2tf32(As[r0 * GST + kk + lc]);
                a[mi][1] = f2tf32(As[(r0 + 8) * GST + kk + lc]);
                a[mi][2] = f2tf32(As[r0 * GST + kk + lc + 4]);
                a[mi][3] = f2tf32(As[(r0 + 8) * GST + kk + lc + 4]);
            }
#pragma unroll
            for (int nj = 0; nj < 4; nj++) {
                int rn = wn + nj * 8 + lr;
                b[nj][0] = f2tf32(Ws[rn * GST + kk + lc]);
                b[nj][1] = f2tf32(Ws[rn * GST + kk + lc + 4]);
            }
#pragma unroll
            for (int mi = 0; mi < 2; mi++)
#pragma unroll
                for (int nj = 0; nj < 4; nj++)
                    mma_tf32(acc[mi][nj], a[mi], b[nj], acc[mi][nj]);
        }
        __syncthreads();
    }

#pragma unroll
    for (int mi = 0; mi < 2; mi++) {
        int row = m0 + wm + mi * 16 + lr;
#pragma unroll
        for (int nj = 0; nj < 4; nj++) {
            int col = n0 + wn + nj * 8 + 2 * lc;
            *(float2*)(C + (size_t)row * N + col) =
                make_float2(acc[mi][nj][0], acc[mi][nj][1]);
            *(float2*)(C + (size_t)(row + 8) * N + col) =
                make_float2(acc[mi][nj][2], acc[mi][nj][3]);
        }
    }
}

// ---------------------------------------------------------------------------
// Pipelined batched MMA GEMM-NN: C_b[M,N] = A_b[M,K] * B_b[K,N], tf32.
// BM=64, BN=64, BK=32. 8 warps (4M x 2N), warp tile 16x32.
// B tile stored [32][72] (stride 72 == 8 mod 32 -> conflict-free col reads).
// Stage: A 64x36 + B 32x72 floats = 18,432 B; 2 stages = 36,864 B static.
// ---------------------------------------------------------------------------
#define NNST_A 36
#define NNST_B 72
#define NN_STAGE (64 * NNST_A + 32 * NNST_B)   // floats

__global__ __launch_bounds__(256, 2)
void gemm_nn_mma(const float* __restrict__ A, const float* __restrict__ B,
                 float* __restrict__ C, int M, int N, int K,
                 size_t strideA, size_t strideB, size_t strideC) {
    __shared__ float sm[2 * NN_STAGE];
    const float* Ab = A + (size_t)blockIdx.z * strideA;
    const float* Bb = B + (size_t)blockIdx.z * strideB;
    float* Cb = C + (size_t)blockIdx.z * strideC;
    const int m0 = blockIdx.y * 64;
    const int n0 = blockIdx.x * 64;
    const int tid = threadIdx.x;
    const int wid = tid >> 5, lane = tid & 31;
    const int lr = lane >> 2, lc = lane & 3;
    const int wm = (wid >> 1) * 16;
    const int wn = (wid & 1) * 32;

    const uint32_t smem_base = (uint32_t)__cvta_generic_to_shared(sm);
    float acc[4][4] = {};
    const int kt = K / 32;

    // prologue
    {
        uint32_t As_u = smem_base;
        uint32_t Bs_u = smem_base + 64 * NNST_A * 4;
#pragma unroll
        for (int t = 0; t < 2; t++) {
            int s = tid + t * 256;                 // 0..511 : A 64 rows x 8 f4
            int r = s >> 3, c = (s & 7) * 4;
            cp_async16(As_u + (r * NNST_A + c) * 4, Ab + (size_t)(m0 + r) * K + c);
        }
#pragma unroll
        for (int t = 0; t < 2; t++) {
            int s = tid + t * 256;                 // 0..511 : B 32 rows x 16 f4
            int r = s >> 4, c = (s & 15) * 4;
            cp_async16(Bs_u + (r * NNST_B + c) * 4, Bb + (size_t)r * N + n0 + c);
        }
    }
    cp_commit();

    for (int it = 0; it < kt; it++) {
        if (it + 1 < kt) {
            int k0 = (it + 1) * 32;
            uint32_t st = smem_base + ((it + 1) & 1) * NN_STAGE * 4;
            uint32_t As_u = st;
            uint32_t Bs_u = st + 64 * NNST_A * 4;
#pragma unroll
            for (int t = 0; t < 2; t++) {
                int s = tid + t * 256;
                int r = s >> 3, c = (s & 7) * 4;
                cp_async16(As_u + (r * NNST_A + c) * 4, Ab + (size_t)(m0 + r) * K + k0 + c);
            }
#pragma unroll
            for (int t = 0; t < 2; t++) {
                int s = tid + t * 256;
                int r = s >> 4, c = (s & 15) * 4;
                cp_async16(Bs_u + (r * NNST_B + c) * 4, Bb + (size_t)(k0 + r) * N + n0 + c);
            }
        }
        cp_commit();
        cp_wait1();
        __syncthreads();

        const float* As = sm + (it & 1) * NN_STAGE;
        const float* Bs = As + 64 * NNST_A;
#pragma unroll
        for (int kk = 0; kk < 32; kk += 8) {
            uint32_t a[4], b[4][2];
            int r0 = wm + lr;
            a[0] = f2tf32(As[r0 * NNST_A + kk + lc]);
            a[1] = f2tf32(As[(r0 + 8) * NNST_A + kk + lc]);
            a[2] = f2tf32(As[r0 * NNST_A + kk + lc + 4]);
            a[3] = f2tf32(As[(r0 + 8) * NNST_A + kk + lc + 4]);
#pragma unroll
            for (int nj = 0; nj < 4; nj++) {
                int rn = wn + nj * 8 + lr;
                b[nj][0] = f2tf32(Bs[(kk + lc) * NNST_B + rn]);
                b[nj][1] = f2tf32(Bs[(kk + lc + 4) * NNST_B + rn]);
            }
#pragma unroll
            for (int nj = 0; nj < 4; nj++)
                mma_tf32(acc[nj], a, b[nj], acc[nj]);
        }
        __syncthreads();
    }

    {
        int row = m0 + wm + lr;
#pragma unroll
        for (int nj = 0; nj < 4; nj++) {
            int col = n0 + wn + nj * 8 + 2 * lc;
            *(float2*)(Cb + (size_t)row * N + col) =
                make_float2(acc[nj][0], acc[nj][1]);
            *(float2*)(Cb + (size_t)(row + 8) * N + col) =
                make_float2(acc[nj][2], acc[nj][3]);
        }
    }
}

// ---------------------------------------------------------------------------
// Fused scores + softmax, register-resident, two-pass (no max needed: scores
// are O(1) by construction; softmax is shift-invariant).
// ---------------------------------------------------------------------------
#define QST 68
#define ATTN_SMEM (2 * 128 * QST * 4)

__global__ __launch_bounds__(256, 2)
void attn_scores_kernel(const float* __restrict__ qh,
                        const float* __restrict__ kh,
                        float* __restrict__ attn_out) {
    extern __shared__ uint32_t smem_u[];
    uint32_t* qs = smem_u;              // [128][QST]
    uint32_t* ks = smem_u + 128 * QST;  // [128][QST]

    const int q0 = blockIdx.x * 128;
    const int h = blockIdx.y;
    const int b = blockIdx.z;
    const int tid = threadIdx.x;
    const int wid = tid >> 5, lane = tid & 31;
    const int lr = lane >> 2, lc = lane & 3;
    const int r0 = wid * 16 + lr;

    const float* qbase = qh + ((size_t)(b * SS + q0)) * DD + h * DK;
#pragma unroll
    for (int s = tid; s < 128 * 16; s += 256) {
        int r = s >> 4, c4 = (s & 15) * 4;
        float4 v = *(const float4*)(qbase + (size_t)r * DD + c4);
        qs[r * QST + c4 + 0] = f2tf32(v.x * 0.125f);
        qs[r * QST + c4 + 1] = f2tf32(v.y * 0.125f);
        qs[r * QST + c4 + 2] = f2tf32(v.z * 0.125f);
        qs[r * QST + c4 + 3] = f2tf32(v.w * 0.125f);
    }

    const float* kbase = kh + ((size_t)b * SS) * DD + h * DK;

    float rsum0 = 0.f, rsum1 = 0.f;

    for (int ck = 0; ck < SS / 128; ck++) {
        __syncthreads();
#pragma unroll
        for (int s = tid; s < 128 * 16; s += 256) {
            int r = s >> 4, c4 = (s & 15) * 4;
            float4 v = *(const float4*)(kbase + (size_t)(ck * 128 + r) * DD + c4);
            ks[r * QST + c4 + 0] = f2tf32(v.x);
            ks[r * QST + c4 + 1] = f2tf32(v.y);
            ks[r * QST + c4 + 2] = f2tf32(v.z);
            ks[r * QST + c4 + 3] = f2tf32(v.w);
        }
        __syncthreads();

        float acc[16][4] = {};
#pragma unroll
        for (int kk = 0; kk < DK; kk += 8) {
            uint32_t a[4];
            a[0] = qs[r0 * QST + kk + lc];
            a[1] = qs[(r0 + 8) * QST + kk + lc];
            a[2] = qs[r0 * QST + kk + lc + 4];
            a[3] = qs[(r0 + 8) * QST + kk + lc + 4];
#pragma unroll
            for (int nj = 0; nj < 16; nj++) {
                uint32_t bf[2];
                int rn = nj * 8 + lr;
                bf[0] = ks[rn * QST + kk + lc];
                bf[1] = ks[rn * QST + kk + lc + 4];
                mma_tf32(acc[nj], a, bf, acc[nj]);
            }
        }
#pragma unroll
        for (int nj = 0; nj < 16; nj++) {
            rsum0 += __expf(acc[nj][0]) + __expf(acc[nj][1]);
            rsum1 += __expf(acc[nj][2]) + __expf(acc[nj][3]);
        }
    }
#pragma unroll
    for (int off = 1; off <= 2; off <<= 1) {
        rsum0 += __shfl_xor_sync(0xffffffffu, rsum0, off);
        rsum1 += __shfl_xor_sync(0xffffffffu, rsum1, off);
    }
    const float inv0 = 1.f / rsum0;
    const float inv1 = 1.f / rsum1;

    float* orow0 = attn_out + (((size_t)(h * NB + b) * SS) + q0 + r0) * SS;
    float* orow1 = orow0 + (size_t)8 * SS;

    for (int ck = 0; ck < SS / 128; ck++) {
        __syncthreads();
#pragma unroll
        for (int s = tid; s < 128 * 16; s += 256) {
            int r = s >> 4, c4 = (s & 15) * 4;
            float4 v = *(const float4*)(kbase + (size_t)(ck * 128 + r) * DD + c4);
            ks[r * QST + c4 + 0] = f2tf32(v.x);
            ks[r * QST + c4 + 1] = f2tf32(v.y);
            ks[r * QST + c4 + 2] = f2tf32(v.z);
            ks[r * QST + c4 + 3] = f2tf32(v.w);
        }
        __syncthreads();

        float acc[16][4] = {};
#pragma unroll
        for (int kk = 0; kk < DK; kk += 8) {
            uint32_t a[4];
            a[0] = qs[r0 * QST + kk + lc];
            a[1] = qs[(r0 + 8) * QST + kk + lc];
            a[2] = qs[r0 * QST + kk + lc + 4];
            a[3] = qs[(r0 + 8) * QST + kk + lc + 4];
#pragma unroll
            for (int nj = 0; nj < 16; nj++) {
                uint32_t bf[2];
                int rn = nj * 8 + lr;
                bf[0] = ks[rn * QST + kk + lc];
                bf[1] = ks[rn * QST + kk + lc + 4];
                mma_tf32(acc[nj], a, bf, acc[nj]);
            }
        }
#pragma unroll
        for (int nj = 0; nj < 16; nj++) {
            int col = ck * 128 + nj * 8 + 2 * lc;
            *(float2*)(orow0 + col) =
                make_float2(__expf(acc[nj][0]) * inv0, __expf(acc[nj][1]) * inv0);
            *(float2*)(orow1 + col) =
                make_float2(__expf(acc[nj][2]) * inv1, __expf(acc[nj][3]) * inv1);
        }
    }
}

// ---------------------------------------------------------------------------
// P_avg, float4-vectorized: pavg[b,q,k] = (1/H) * sum_h attn[h,b,q,k]
// ---------------------------------------------------------------------------
__global__ void pavg_kernel(const float4* __restrict__ attn, float4* __restrict__ pavg) {
    size_t idx = (size_t)blockIdx.x * 256 + threadIdx.x;  // < 2M (NB*SS*SS/4)
    int b = (int)(idx >> 18);
    size_t rem = idx & ((1u << 18) - 1);
    float4 s = make_float4(0.f, 0.f, 0.f, 0.f);
#pragma unroll
    for (int h = 0; h < NH; h++) {
        float4 t = attn[(size_t)(h * NB + b) * (SS * SS / 4) + rem];
        s.x += t.x; s.y += t.y; s.z += t.z; s.w += t.w;
    }
    s.x *= 0.125f; s.y *= 0.125f; s.z *= 0.125f; s.w *= 0.125f;
    pavg[idx] = s;
}

// ---------------------------------------------------------------------------
extern "C" void kernel_launch(void* const* d_in, const int* in_sizes, int n_in,
                              void* d_out, int out_size) {
    const float* q  = (const float*)d_in[0];
    const float* k  = (const float*)d_in[1];
    const float* v  = (const float*)d_in[2];
    const float* Wq = (const float*)d_in[3];
    const float* Wk = (const float*)d_in[4];
    const float* Wv = (const float*)d_in[5];
    const float* Wo = (const float*)d_in[6];
    float* out  = (float*)d_out;
    float* attn = out + OUT_ELEMS;

    float *qh, *kh, *vs, *pavg, *head;
    cudaGetSymbolAddress((void**)&qh,   g_qh);
    cudaGetSymbolAddress((void**)&kh,   g_kh);
    cudaGetSymbolAddress((void**)&vs,   g_vs);
    cudaGetSymbolAddress((void**)&pavg, g_pavg);
    cudaGetSymbolAddress((void**)&head, g_head);

    cudaFuncSetAttribute(attn_scores_kernel,
                         cudaFuncAttributeMaxDynamicSharedMemorySize, ATTN_SMEM);
    cudaFuncSetAttribute(gemm_nt_mma2,
                         cudaFuncAttributeMaxDynamicSharedMemorySize, PROJ_SMEM);

    // Projections via pipelined tf32 MMA
    gemm_nt_mma2<<<dim3(DD / 64, MROWS / 128), 256, PROJ_SMEM>>>(q, Wq, qh, MROWS, DD, DD);
    gemm_nt_mma2<<<dim3(DD / 64, MROWS / 128), 256, PROJ_SMEM>>>(k, Wk, kh, MROWS, DD, DD);
    gemm_nt_mma2<<<dim3(DK / 64, MROWS / 128), 256, PROJ_SMEM>>>(v, Wv, vs, MROWS, DK, DD);

    // Scores + softmax -> attn (in d_out)
    attn_scores_kernel<<<dim3(SS / 128, NH, NB), 256, ATTN_SMEM>>>(qh, kh, attn);

    // Mean over heads (float4)
    pavg_kernel<<<(NB * SS * SS / 4) / 256, 256>>>((const float4*)attn, (float4*)pavg);

    // head = P_avg @ vs (per batch), pipelined tf32 MMA
    gemm_nn_mma<<<dim3(1, SS / 64, NB), 256>>>(
        pavg, vs, head, SS, DK, SS,
        (size_t)SS * SS, (size_t)SS * DK, (size_t)SS * DK);

    // out = head @ Wo^T, pipelined tf32 MMA (K=64)
    gemm_nt_mma2<<<dim3(DD / 64, MROWS / 128), 256, PROJ_SMEM>>>(head, Wo, out, MROWS, DD, DK);
}

// round 7
// speedup vs baseline: 2.5877x; 1.0938x over previous
#include <cuda_runtime.h>
#include <cuda_bf16.h>
#include <math.h>
#include <stdint.h>

// Problem constants
#define NB 8
#define SS 1024
#define DD 512
#define NH 8
#define DK 64
#define MROWS (NB * SS)          // 8192
#define OUT_ELEMS (NB * SS * DD) // 4194304

// Scratch (no allocations allowed)
__device__ float g_qh[MROWS * DD];       // [B,S,H*DK]
__device__ float g_kh[MROWS * DD];
__device__ float g_vs[MROWS * DK];       // [B,S,DK]
__device__ float g_pavg[NB * SS * SS];   // [B,Sq,Sk]
__device__ float g_head[MROWS * DK];
__device__ float g_rsuminv[NH * NB * SS]; // 1/rowsum per (h,b,q)

// ---------------------------------------------------------------------------
// tf32 / async helpers
// ---------------------------------------------------------------------------
__device__ __forceinline__ uint32_t f2tf32(float x) {
    uint32_t r;
    asm("cvt.rna.tf32.f32 %0, %1;" : "=r"(r) : "f"(x));
    return r;
}

__device__ __forceinline__ void mma_tf32(float* d, const uint32_t* a,
                                         const uint32_t* b, const float* c) {
    asm volatile(
        "mma.sync.aligned.m16n8k8.row.col.f32.tf32.tf32.f32 "
        "{%0,%1,%2,%3}, {%4,%5,%6,%7}, {%8,%9}, {%10,%11,%12,%13};"
        : "=f"(d[0]), "=f"(d[1]), "=f"(d[2]), "=f"(d[3])
        : "r"(a[0]), "r"(a[1]), "r"(a[2]), "r"(a[3]),
          "r"(b[0]), "r"(b[1]),
          "f"(c[0]), "f"(c[1]), "f"(c[2]), "f"(c[3]));
}

__device__ __forceinline__ void cp_async16(uint32_t dst, const void* src) {
    asm volatile("cp.async.cg.shared.global [%0], [%1], 16;" :: "r"(dst), "l"(src));
}
__device__ __forceinline__ void cp_commit() {
    asm volatile("cp.async.commit_group;");
}
__device__ __forceinline__ void cp_wait1() {
    asm volatile("cp.async.wait_group 1;");
}

// ---------------------------------------------------------------------------
// Pipelined MMA GEMM-NT: C[M,N] = A[M,K] * W[N,K]^T (row-major), tf32.
// BM=128, BN=64, BK=32, 2-stage cp.async double buffer.
// ---------------------------------------------------------------------------
#define GST 36
#define PROJ_STAGE (192 * GST)
#define PROJ_SMEM (2 * PROJ_STAGE * 4)

__global__ __launch_bounds__(256, 2)
void gemm_nt_mma2(const float* __restrict__ A, const float* __restrict__ W,
                  float* __restrict__ C, int M, int N, int K) {
    extern __shared__ float sm[];
    const int m0 = blockIdx.y * 128;
    const int n0 = blockIdx.x * 64;
    const int tid = threadIdx.x;
    const int wid = tid >> 5, lane = tid & 31;
    const int lr = lane >> 2, lc = lane & 3;
    const int wm = (wid >> 1) * 32;
    const int wn = (wid & 1) * 32;

    const uint32_t smem_base = (uint32_t)__cvta_generic_to_shared(sm);

    float acc[2][4][4] = {};
    const int kt = K / 32;

    {
        uint32_t As_u = smem_base;
        uint32_t Ws_u = smem_base + 128 * GST * 4;
#pragma unroll
        for (int t = 0; t < 4; t++) {
            int s = tid + t * 256;
            int r = s >> 3, c = (s & 7) * 4;
            cp_async16(As_u + (r * GST + c) * 4, A + (size_t)(m0 + r) * K + c);
        }
#pragma unroll
        for (int t = 0; t < 2; t++) {
            int s = tid + t * 256;
            int r = s >> 3, c = (s & 7) * 4;
            cp_async16(Ws_u + (r * GST + c) * 4, W + (size_t)(n0 + r) * K + c);
        }
    }
    cp_commit();

    for (int it = 0; it < kt; it++) {
        if (it + 1 < kt) {
            int k0 = (it + 1) * 32;
            uint32_t st = smem_base + ((it + 1) & 1) * PROJ_STAGE * 4;
            uint32_t As_u = st;
            uint32_t Ws_u = st + 128 * GST * 4;
#pragma unroll
            for (int t = 0; t < 4; t++) {
                int s = tid + t * 256;
                int r = s >> 3, c = (s & 7) * 4;
                cp_async16(As_u + (r * GST + c) * 4, A + (size_t)(m0 + r) * K + k0 + c);
            }
#pragma unroll
            for (int t = 0; t < 2; t++) {
                int s = tid + t * 256;
                int r = s >> 3, c = (s & 7) * 4;
                cp_async16(Ws_u + (r * GST + c) * 4, W + (size_t)(n0 + r) * K + k0 + c);
            }
        }
        cp_commit();
        cp_wait1();
        __syncthreads();

        const float* As = sm + (it & 1) * PROJ_STAGE;
        const float* Ws = As + 128 * GST;
#pragma unroll
        for (int kk = 0; kk < 32; kk += 8) {
            uint32_t a[2][4], b[4][2];
#pragma unroll
            for (int mi = 0; mi < 2; mi++) {
                int r0 = wm + mi * 16 + lr;
                a[mi][0] = f2tf32(As[r0 * GST + kk + lc]);
                a[mi][1] = f2tf32(As[(r0 + 8) * GST + kk + lc]);
                a[mi][2] = f2tf32(As[r0 * GST + kk + lc + 4]);
                a[mi][3] = f2tf32(As[(r0 + 8) * GST + kk + lc + 4]);
            }
#pragma unroll
            for (int nj = 0; nj < 4; nj++) {
                int rn = wn + nj * 8 + lr;
                b[nj][0] = f2tf32(Ws[rn * GST + kk + lc]);
                b[nj][1] = f2tf32(Ws[rn * GST + kk + lc + 4]);
            }
#pragma unroll
            for (int mi = 0; mi < 2; mi++)
#pragma unroll
                for (int nj = 0; nj < 4; nj++)
                    mma_tf32(acc[mi][nj], a[mi], b[nj], acc[mi][nj]);
        }
        __syncthreads();
    }

#pragma unroll
    for (int mi = 0; mi < 2; mi++) {
        int row = m0 + wm + mi * 16 + lr;
#pragma unroll
        for (int nj = 0; nj < 4; nj++) {
            int col = n0 + wn + nj * 8 + 2 * lc;
            *(float2*)(C + (size_t)row * N + col) =
                make_float2(acc[mi][nj][0], acc[mi][nj][1]);
            *(float2*)(C + (size_t)(row + 8) * N + col) =
                make_float2(acc[mi][nj][2], acc[mi][nj][3]);
        }
    }
}

// ---------------------------------------------------------------------------
// Pipelined batched MMA GEMM-NN: C_b[M,N] = A_b[M,K] * B_b[K,N], tf32.
// ---------------------------------------------------------------------------
#define NNST_A 36
#define NNST_B 72
#define NN_STAGE (64 * NNST_A + 32 * NNST_B)

__global__ __launch_bounds__(256, 2)
void gemm_nn_mma(const float* __restrict__ A, const float* __restrict__ B,
                 float* __restrict__ C, int M, int N, int K,
                 size_t strideA, size_t strideB, size_t strideC) {
    __shared__ float sm[2 * NN_STAGE];
    const float* Ab = A + (size_t)blockIdx.z * strideA;
    const float* Bb = B + (size_t)blockIdx.z * strideB;
    float* Cb = C + (size_t)blockIdx.z * strideC;
    const int m0 = blockIdx.y * 64;
    const int n0 = blockIdx.x * 64;
    const int tid = threadIdx.x;
    const int wid = tid >> 5, lane = tid & 31;
    const int lr = lane >> 2, lc = lane & 3;
    const int wm = (wid >> 1) * 16;
    const int wn = (wid & 1) * 32;

    const uint32_t smem_base = (uint32_t)__cvta_generic_to_shared(sm);
    float acc[4][4] = {};
    const int kt = K / 32;

    {
        uint32_t As_u = smem_base;
        uint32_t Bs_u = smem_base + 64 * NNST_A * 4;
#pragma unroll
        for (int t = 0; t < 2; t++) {
            int s = tid + t * 256;
            int r = s >> 3, c = (s & 7) * 4;
            cp_async16(As_u + (r * NNST_A + c) * 4, Ab + (size_t)(m0 + r) * K + c);
        }
#pragma unroll
        for (int t = 0; t < 2; t++) {
            int s = tid + t * 256;
            int r = s >> 4, c = (s & 15) * 4;
            cp_async16(Bs_u + (r * NNST_B + c) * 4, Bb + (size_t)r * N + n0 + c);
        }
    }
    cp_commit();

    for (int it = 0; it < kt; it++) {
        if (it + 1 < kt) {
            int k0 = (it + 1) * 32;
            uint32_t st = smem_base + ((it + 1) & 1) * NN_STAGE * 4;
            uint32_t As_u = st;
            uint32_t Bs_u = st + 64 * NNST_A * 4;
#pragma unroll
            for (int t = 0; t < 2; t++) {
                int s = tid + t * 256;
                int r = s >> 3, c = (s & 7) * 4;
                cp_async16(As_u + (r * NNST_A + c) * 4, Ab + (size_t)(m0 + r) * K + k0 + c);
            }
#pragma unroll
            for (int t = 0; t < 2; t++) {
                int s = tid + t * 256;
                int r = s >> 4, c = (s & 15) * 4;
                cp_async16(Bs_u + (r * NNST_B + c) * 4, Bb + (size_t)(k0 + r) * N + n0 + c);
            }
        }
        cp_commit();
        cp_wait1();
        __syncthreads();

        const float* As = sm + (it & 1) * NN_STAGE;
        const float* Bs = As + 64 * NNST_A;
#pragma unroll
        for (int kk = 0; kk < 32; kk += 8) {
            uint32_t a[4], b[4][2];
            int r0 = wm + lr;
            a[0] = f2tf32(As[r0 * NNST_A + kk + lc]);
            a[1] = f2tf32(As[(r0 + 8) * NNST_A + kk + lc]);
            a[2] = f2tf32(As[r0 * NNST_A + kk + lc + 4]);
            a[3] = f2tf32(As[(r0 + 8) * NNST_A + kk + lc + 4]);
#pragma unroll
            for (int nj = 0; nj < 4; nj++) {
                int rn = wn + nj * 8 + lr;
                b[nj][0] = f2tf32(Bs[(kk + lc) * NNST_B + rn]);
                b[nj][1] = f2tf32(Bs[(kk + lc + 4) * NNST_B + rn]);
            }
#pragma unroll
            for (int nj = 0; nj < 4; nj++)
                mma_tf32(acc[nj], a, b[nj], acc[nj]);
        }
        __syncthreads();
    }

    {
        int row = m0 + wm + lr;
#pragma unroll
        for (int nj = 0; nj < 4; nj++) {
            int col = n0 + wn + nj * 8 + 2 * lc;
            *(float2*)(Cb + (size_t)row * N + col) =
                make_float2(acc[nj][0], acc[nj][1]);
            *(float2*)(Cb + (size_t)(row + 8) * N + col) =
                make_float2(acc[nj][2], acc[nj][3]);
        }
    }
}

// ---------------------------------------------------------------------------
// Pass 1: row sums of exp(score) only. Block = (128 q rows, h, b), 8 warps.
// Warp tile 32q x 64k (wq = wid>>1, wk = wid&1): 24 LDS per 8k-slice.
// Writes 1/rowsum to g_rsuminv. No attn store.
// Smem: qs[128][68] + ks[128][68] tf32 = 69,632 B dynamic (+1KB static).
// ---------------------------------------------------------------------------
#define QST 68
#define SUMS_SMEM (2 * 128 * QST * 4)

__global__ __launch_bounds__(256, 2)
void attn_sums_kernel(const float* __restrict__ qh,
                      const float* __restrict__ kh,
                      float* __restrict__ rsuminv) {
    extern __shared__ uint32_t smem_u[];
    uint32_t* qs = smem_u;              // [128][QST]
    uint32_t* ks = smem_u + 128 * QST;  // [128][QST]
    __shared__ float ssum[2][128];

    const int q0 = blockIdx.x * 128;
    const int h = blockIdx.y;
    const int b = blockIdx.z;
    const int tid = threadIdx.x;
    const int wid = tid >> 5, lane = tid & 31;
    const int lr = lane >> 2, lc = lane & 3;
    const int wq = wid >> 1, wk = wid & 1;

    const float* qbase = qh + ((size_t)(b * SS + q0)) * DD + h * DK;
#pragma unroll
    for (int s = tid; s < 128 * 16; s += 256) {
        int r = s >> 4, c4 = (s & 15) * 4;
        float4 v = *(const float4*)(qbase + (size_t)r * DD + c4);
        qs[r * QST + c4 + 0] = f2tf32(v.x * 0.125f);
        qs[r * QST + c4 + 1] = f2tf32(v.y * 0.125f);
        qs[r * QST + c4 + 2] = f2tf32(v.z * 0.125f);
        qs[r * QST + c4 + 3] = f2tf32(v.w * 0.125f);
    }

    const float* kbase = kh + ((size_t)b * SS) * DD + h * DK;

    float rs[2][2] = {};  // [mi][row-half]

    for (int ck = 0; ck < SS / 128; ck++) {
        __syncthreads();
#pragma unroll
        for (int s = tid; s < 128 * 16; s += 256) {
            int r = s >> 4, c4 = (s & 15) * 4;
            float4 v = *(const float4*)(kbase + (size_t)(ck * 128 + r) * DD + c4);
            ks[r * QST + c4 + 0] = f2tf32(v.x);
            ks[r * QST + c4 + 1] = f2tf32(v.y);
            ks[r * QST + c4 + 2] = f2tf32(v.z);
            ks[r * QST + c4 + 3] = f2tf32(v.w);
        }
        __syncthreads();

        float acc[2][8][4] = {};
#pragma unroll
        for (int kk = 0; kk < DK; kk += 8) {
            uint32_t a[2][4];
#pragma unroll
            for (int mi = 0; mi < 2; mi++) {
                int r0 = wq * 32 + mi * 16 + lr;
                a[mi][0] = qs[r0 * QST + kk + lc];
                a[mi][1] = qs[(r0 + 8) * QST + kk + lc];
                a[mi][2] = qs[r0 * QST + kk + lc + 4];
                a[mi][3] = qs[(r0 + 8) * QST + kk + lc + 4];
            }
#pragma unroll
            for (int nj = 0; nj < 8; nj++) {
                int rn = wk * 64 + nj * 8 + lr;
                uint32_t bf[2];
                bf[0] = ks[rn * QST + kk + lc];
                bf[1] = ks[rn * QST + kk + lc + 4];
                mma_tf32(acc[0][nj], a[0], bf, acc[0][nj]);
                mma_tf32(acc[1][nj], a[1], bf, acc[1][nj]);
            }
        }
#pragma unroll
        for (int mi = 0; mi < 2; mi++)
#pragma unroll
            for (int nj = 0; nj < 8; nj++) {
                rs[mi][0] += __expf(acc[mi][nj][0]) + __expf(acc[mi][nj][1]);
                rs[mi][1] += __expf(acc[mi][nj][2]) + __expf(acc[mi][nj][3]);
            }
    }
    // reduce over the 4 lc lanes sharing each row
#pragma unroll
    for (int off = 1; off <= 2; off <<= 1) {
#pragma unroll
        for (int mi = 0; mi < 2; mi++) {
            rs[mi][0] += __shfl_xor_sync(0xffffffffu, rs[mi][0], off);
            rs[mi][1] += __shfl_xor_sync(0xffffffffu, rs[mi][1], off);
        }
    }
    if (lc == 0) {
#pragma unroll
        for (int mi = 0; mi < 2; mi++) {
            ssum[wk][wq * 32 + mi * 16 + lr] = rs[mi][0];
            ssum[wk][wq * 32 + mi * 16 + lr + 8] = rs[mi][1];
        }
    }
    __syncthreads();
    if (tid < 128)
        rsuminv[(size_t)(h * NB + b) * SS + q0 + tid] =
            1.f / (ssum[0][tid] + ssum[1][tid]);
}

// ---------------------------------------------------------------------------
// Pass 2: recompute scores per head, write normalized attn, accumulate P_avg
// in registers across all 8 heads, write pavg. Block = (64 q rows, one
// 128-key chunk, b); 8 warps, warp tile 16q x 64k.
// Smem: qs[64][68] + ks[128][68] = 52,224 B dynamic.
// ---------------------------------------------------------------------------
#define WRITE_SMEM ((64 * QST + 128 * QST) * 4)

__global__ __launch_bounds__(256, 2)
void attn_write_kernel(const float* __restrict__ qh,
                       const float* __restrict__ kh,
                       const float* __restrict__ rsuminv,
                       float* __restrict__ attn_out,
                       float* __restrict__ pavg) {
    extern __shared__ uint32_t smem_u[];
    uint32_t* qs = smem_u;             // [64][QST]
    uint32_t* ks = smem_u + 64 * QST;  // [128][QST]

    const int q0 = blockIdx.x * 64;
    const int ck = blockIdx.y;
    const int b = blockIdx.z;
    const int kb = ck * 128;
    const int tid = threadIdx.x;
    const int wid = tid >> 5, lane = tid & 31;
    const int lr = lane >> 2, lc = lane & 3;
    const int wq = wid >> 1, wk = wid & 1;
    const int r0l = wq * 16 + lr;  // local q row (and +8)

    float pav[8][4] = {};

    for (int h = 0; h < NH; h++) {
        __syncthreads();
        // load 64 Q rows for this head (scaled, tf32)
        const float* qbase = qh + ((size_t)(b * SS + q0)) * DD + h * DK;
#pragma unroll
        for (int s = tid; s < 64 * 16; s += 256) {
            int r = s >> 4, c4 = (s & 15) * 4;
            float4 v = *(const float4*)(qbase + (size_t)r * DD + c4);
            qs[r * QST + c4 + 0] = f2tf32(v.x * 0.125f);
            qs[r * QST + c4 + 1] = f2tf32(v.y * 0.125f);
            qs[r * QST + c4 + 2] = f2tf32(v.z * 0.125f);
            qs[r * QST + c4 + 3] = f2tf32(v.w * 0.125f);
        }
        // load 128-key chunk for this head
        const float* kbase = kh + ((size_t)(b * SS + kb)) * DD + h * DK;
#pragma unroll
        for (int s = tid; s < 128 * 16; s += 256) {
            int r = s >> 4, c4 = (s & 15) * 4;
            float4 v = *(const float4*)(kbase + (size_t)r * DD + c4);
            ks[r * QST + c4 + 0] = f2tf32(v.x);
            ks[r * QST + c4 + 1] = f2tf32(v.y);
            ks[r * QST + c4 + 2] = f2tf32(v.z);
            ks[r * QST + c4 + 3] = f2tf32(v.w);
        }
        __syncthreads();

        float acc[8][4] = {};
#pragma unroll
        for (int kk = 0; kk < DK; kk += 8) {
            uint32_t a[4];
            a[0] = qs[r0l * QST + kk + lc];
            a[1] = qs[(r0l + 8) * QST + kk + lc];
            a[2] = qs[r0l * QST + kk + lc + 4];
            a[3] = qs[(r0l + 8) * QST + kk + lc + 4];
#pragma unroll
            for (int nj = 0; nj < 8; nj++) {
                int rn = wk * 64 + nj * 8 + lr;
                uint32_t bf[2];
                bf[0] = ks[rn * QST + kk + lc];
                bf[1] = ks[rn * QST + kk + lc + 4];
                mma_tf32(acc[nj], a, bf, acc[nj]);
            }
        }

        const float inv0 = rsuminv[(size_t)(h * NB + b) * SS + q0 + r0l];
        const float inv1 = rsuminv[(size_t)(h * NB + b) * SS + q0 + r0l + 8];
        float* orow0 = attn_out + (((size_t)(h * NB + b) * SS) + q0 + r0l) * SS + kb;
        float* orow1 = orow0 + (size_t)8 * SS;
#pragma unroll
        for (int nj = 0; nj < 8; nj++) {
            int col = wk * 64 + nj * 8 + 2 * lc;
            float e0 = __expf(acc[nj][0]) * inv0;
            float e1 = __expf(acc[nj][1]) * inv0;
            float e2 = __expf(acc[nj][2]) * inv1;
            float e3 = __expf(acc[nj][3]) * inv1;
            *(float2*)(orow0 + col) = make_float2(e0, e1);
            *(float2*)(orow1 + col) = make_float2(e2, e3);
            pav[nj][0] += e0; pav[nj][1] += e1;
            pav[nj][2] += e2; pav[nj][3] += e3;
        }
    }

    // write P_avg for this (b, q-block, chunk)
    float* prow0 = pavg + ((size_t)b * SS + q0 + r0l) * SS + kb;
    float* prow1 = prow0 + (size_t)8 * SS;
#pragma unroll
    for (int nj = 0; nj < 8; nj++) {
        int col = wk * 64 + nj * 8 + 2 * lc;
        *(float2*)(prow0 + col) = make_float2(pav[nj][0] * 0.125f, pav[nj][1] * 0.125f);
        *(float2*)(prow1 + col) = make_float2(pav[nj][2] * 0.125f, pav[nj][3] * 0.125f);
    }
}

// ---------------------------------------------------------------------------
extern "C" void kernel_launch(void* const* d_in, const int* in_sizes, int n_in,
                              void* d_out, int out_size) {
    const float* q  = (const float*)d_in[0];
    const float* k  = (const float*)d_in[1];
    const float* v  = (const float*)d_in[2];
    const float* Wq = (const float*)d_in[3];
    const float* Wk = (const float*)d_in[4];
    const float* Wv = (const float*)d_in[5];
    const float* Wo = (const float*)d_in[6];
    float* out  = (float*)d_out;
    float* attn = out + OUT_ELEMS;

    float *qh, *kh, *vs, *pavg, *head, *rsuminv;
    cudaGetSymbolAddress((void**)&qh,      g_qh);
    cudaGetSymbolAddress((void**)&kh,      g_kh);
    cudaGetSymbolAddress((void**)&vs,      g_vs);
    cudaGetSymbolAddress((void**)&pavg,    g_pavg);
    cudaGetSymbolAddress((void**)&head,    g_head);
    cudaGetSymbolAddress((void**)&rsuminv, g_rsuminv);

    cudaFuncSetAttribute(gemm_nt_mma2,
                         cudaFuncAttributeMaxDynamicSharedMemorySize, PROJ_SMEM);
    cudaFuncSetAttribute(attn_sums_kernel,
                         cudaFuncAttributeMaxDynamicSharedMemorySize, SUMS_SMEM);
    cudaFuncSetAttribute(attn_write_kernel,
                         cudaFuncAttributeMaxDynamicSharedMemorySize, WRITE_SMEM);

    // Projections via pipelined tf32 MMA
    gemm_nt_mma2<<<dim3(DD / 64, MROWS / 128), 256, PROJ_SMEM>>>(q, Wq, qh, MROWS, DD, DD);
    gemm_nt_mma2<<<dim3(DD / 64, MROWS / 128), 256, PROJ_SMEM>>>(k, Wk, kh, MROWS, DD, DD);
    gemm_nt_mma2<<<dim3(DK / 64, MROWS / 128), 256, PROJ_SMEM>>>(v, Wv, vs, MROWS, DK, DD);

    // Pass 1: row-sum inverses
    attn_sums_kernel<<<dim3(SS / 128, NH, NB), 256, SUMS_SMEM>>>(qh, kh, rsuminv);

    // Pass 2: normalized attn + fused P_avg
    attn_write_kernel<<<dim3(SS / 64, SS / 128, NB), 256, WRITE_SMEM>>>(
        qh, kh, rsuminv, attn, pavg);

    // head = P_avg @ vs (per batch), pipelined tf32 MMA
    gemm_nn_mma<<<dim3(1, SS / 64, NB), 256>>>(
        pavg, vs, head, SS, DK, SS,
        (size_t)SS * SS, (size_t)SS * DK, (size_t)SS * DK);

    // out = head @ Wo^T, pipelined tf32 MMA (K=64)
    gemm_nt_mma2<<<dim3(DD / 64, MROWS / 128), 256, PROJ_SMEM>>>(head, Wo, out, MROWS, DD, DK);
}